// round 3
// baseline (speedup 1.0000x reference)
#include <cuda_runtime.h>
#include <math.h>

#define S_  2048
#define B_  8
#define E_  1024
#define SB_ (S_*B_)
#define G4_ (4*E_)

/* ---------------- static device scratch (no runtime allocation) ---------------- */
__device__ float g_bias_sum[G4_];
__device__ float g_xln  [SB_*E_];
__device__ float g_gx   [(size_t)SB_*G4_];      /* 256 MB */
__device__ float g_rnn  [SB_*E_];
__device__ float g_mh   [SB_*E_];
__device__ float g_hmid [SB_*E_];
__device__ float g_qpre [SB_*E_];
__device__ float g_query[SB_*E_];
__device__ float g_qsc  [SB_*E_];
__device__ float g_ksc  [SB_*E_];
__device__ float g_vsc  [SB_*E_];
__device__ float g_scores[(size_t)B_*S_*S_];    /* 128 MB */
__device__ float g_h2   [SB_*E_];
__device__ float g_xff  [SB_*E_];
__device__ float g_lnffo[SB_*E_];
__device__ float g_tbuf [2*E_];
__device__ float g_vsgv [E_];
__device__ float g_hbuf [2][B_*E_];
__device__ unsigned g_bar_cnt;
__device__ volatile unsigned g_bar_gen;

__device__ __forceinline__ float fsigm(float x){ return 1.0f/(1.0f+__expf(-x)); }
__device__ __forceinline__ float psigm(float x){ return 1.0f/(1.0f+expf(-x)); }

/* ---------------- LayerNorm over last dim (E=1024), one block per row ---------- */
__global__ void __launch_bounds__(256) ln_kernel(const float* __restrict__ in,
                                                 float* __restrict__ out,
                                                 const float* __restrict__ gamma,
                                                 const float* __restrict__ beta)
{
    long row = blockIdx.x;
    const float4* x = (const float4*)(in + row*E_);
    int t = threadIdx.x;
    float4 v = x[t];
    float s = v.x+v.y+v.z+v.w;
    float q = v.x*v.x+v.y*v.y+v.z*v.z+v.w*v.w;
    #pragma unroll
    for (int o=16;o;o>>=1){ s += __shfl_xor_sync(~0u,s,o); q += __shfl_xor_sync(~0u,q,o); }
    __shared__ float ss[8], sq[8];
    int w = t>>5, l = t&31;
    if (l==0){ ss[w]=s; sq[w]=q; }
    __syncthreads();
    if (t<32){
        float a = (l<8)? ss[l]:0.f, b = (l<8)? sq[l]:0.f;
        #pragma unroll
        for (int o=4;o;o>>=1){ a += __shfl_xor_sync(~0u,a,o); b += __shfl_xor_sync(~0u,b,o); }
        if (l==0){ ss[0]=a; sq[0]=b; }
    }
    __syncthreads();
    float mean = ss[0]*(1.0f/E_);
    float var  = sq[0]*(1.0f/E_) - mean*mean;
    float inv  = rsqrtf(fmaxf(var,0.f)+1e-12f);
    float4 g = ((const float4*)gamma)[t];
    float4 b = ((const float4*)beta)[t];
    float4 o;
    o.x=(v.x-mean)*inv*g.x+b.x; o.y=(v.y-mean)*inv*g.y+b.y;
    o.z=(v.z-mean)*inv*g.z+b.z; o.w=(v.w-mean)*inv*g.w+b.w;
    ((float4*)(out + row*E_))[t] = o;
}

/* ---------------- fp32 GEMM 128x128, K-tile 8, 8x8/thread, reg prefetch -------- */
__global__ void __launch_bounds__(256) gemm_f32(
    const float* __restrict__ A, const float* __restrict__ B,
    const float* __restrict__ bias, const float* __restrict__ extra,
    float* __restrict__ C, int M, int N, int K,
    int lda, int ldb, int ldc, int ldx,
    long sA, long sB, long sC, long sX, int bT, int mode, float alpha)
{
    __shared__ float As[8][128];
    __shared__ float Bs[8][128];
    A += (long)blockIdx.z * sA;
    B += (long)blockIdx.z * sB;
    C += (long)blockIdx.z * sC;
    if (extra) extra += (long)blockIdx.z * sX;
    const int tid = threadIdx.x;
    const int m0 = blockIdx.y*128, n0 = blockIdx.x*128;
    const int lr = tid>>1, lk = (tid&1)*4;
    const int nk = tid>>5, nn = (tid&31)*4;
    const int tx = tid&15, ty = tid>>4;

    float acc[8][8];
    #pragma unroll
    for (int i=0;i<8;i++)
        #pragma unroll
        for (int j=0;j<8;j++) acc[i][j]=0.f;

    float4 ar = *(const float4*)(A + (long)(m0+lr)*lda + lk);
    float4 br = bT ? *(const float4*)(B + (long)(n0+lr)*ldb + lk)
                   : *(const float4*)(B + (long)nk*ldb + n0 + nn);

    for (int k0=0;k0<K;k0+=8){
        As[lk+0][lr]=ar.x; As[lk+1][lr]=ar.y; As[lk+2][lr]=ar.z; As[lk+3][lr]=ar.w;
        if (bT){ Bs[lk+0][lr]=br.x; Bs[lk+1][lr]=br.y; Bs[lk+2][lr]=br.z; Bs[lk+3][lr]=br.w; }
        else   { *(float4*)&Bs[nk][nn] = br; }
        __syncthreads();
        if (k0+8 < K){
            ar = *(const float4*)(A + (long)(m0+lr)*lda + k0+8+lk);
            br = bT ? *(const float4*)(B + (long)(n0+lr)*ldb + k0+8+lk)
                    : *(const float4*)(B + (long)(k0+8+nk)*ldb + n0 + nn);
        }
        #pragma unroll
        for (int kk=0;kk<8;kk++){
            float af[8], bf[8];
            *(float4*)(af)   = *(const float4*)&As[kk][ty*8];
            *(float4*)(af+4) = *(const float4*)&As[kk][ty*8+4];
            *(float4*)(bf)   = *(const float4*)&Bs[kk][tx*8];
            *(float4*)(bf+4) = *(const float4*)&Bs[kk][tx*8+4];
            #pragma unroll
            for (int i=0;i<8;i++)
                #pragma unroll
                for (int j=0;j<8;j++) acc[i][j] = fmaf(af[i], bf[j], acc[i][j]);
        }
        __syncthreads();
    }
    #pragma unroll
    for (int i=0;i<8;i++){
        long m = m0 + ty*8 + i;
        #pragma unroll
        for (int j=0;j<8;j++){
            long n = n0 + tx*8 + j;
            float v = acc[i][j]*alpha;
            if (bias) v += bias[n];
            if (mode==3) v = v*fsigm(1.702f*v);
            if (extra) v += extra[m*ldx + n];
            C[m*ldc + n] = v;
        }
    }
}

/* ---------------- small prep kernels ------------------------------------------ */
__global__ void bias_sum_k(const float* __restrict__ a, const float* __restrict__ b){
    int i = blockIdx.x*256 + threadIdx.x;
    if (i < G4_) g_bias_sum[i] = a[i] + b[i];
}
__global__ void __launch_bounds__(256) vs_proj_k(const float* __restrict__ vs_p,
                                                 const float* __restrict__ op_W,
                                                 const float* __restrict__ op_b){
    int j = blockIdx.x*8 + (threadIdx.x>>5);
    int l = threadIdx.x & 31;
    const float* w = op_W + (long)j*E_;
    float acc = 0.f;
    for (int k=l; k<E_; k+=32) acc += psigm(vs_p[k]) * w[k];
    #pragma unroll
    for (int o=16;o;o>>=1) acc += __shfl_xor_sync(~0u,acc,o);
    if (l==0) g_tbuf[j] = acc + op_b[j];
}
__global__ void vs_gate_k(){
    int e = blockIdx.x*256 + threadIdx.x;
    if (e < E_) g_vsgv[e] = psigm(g_tbuf[E_+e]) * tanhf(g_tbuf[e]);
}
__global__ void zero_state_k(){
    int i = blockIdx.x*256 + threadIdx.x;
    if (i < B_*E_){ g_hbuf[0][i] = 0.f; g_hbuf[1][i] = 0.f; }
}
__global__ void scale_qkv_k(const float* __restrict__ qs, const float* __restrict__ ks){
    for (long i = (long)blockIdx.x*blockDim.x + threadIdx.x; i < (long)SB_*E_;
         i += (long)gridDim.x*blockDim.x){
        int e = (int)(i & (E_-1));
        g_qsc[i] = fsigm(qs[e]) * g_query[i];
        float m = g_mh[i];
        g_ksc[i] = fsigm(ks[e]) * m;
        g_vsc[i] = g_vsgv[e] * m;
    }
}

/* ---------------- persistent LSTM: 128 blocks x 256 threads -------------------- */
/* Block bid owns hidden units e in [8*bid, 8*bid+8)  -> 32 gate rows.
   SMEM: wT[k4][32] float4 (128 KB, loaded once), h (32 KB), red (8 KB), gates.
   Warp s = K-slice (k4 in [s*32, s*32+32)), lane = row r (g*8+el).
   Thread computes partial dots for its row over all 8 batches with fma.rn.f32x2.
   Grid barrier (generation counter, monotonic -> CUDA-graph-replay-safe).       */
#define LSTM_BLOCKS 128
#define LSTM_SMEM_BYTES (131072 + 32768 + 8192 + 1024 + 256)

__device__ __forceinline__ void fma2(unsigned long long &acc,
                                     unsigned long long a, unsigned long long b){
    asm("fma.rn.f32x2 %0, %1, %2, %0;" : "+l"(acc) : "l"(a), "l"(b));
}
__device__ __forceinline__ float f2sum(unsigned long long v){
    return __uint_as_float((unsigned)v) + __uint_as_float((unsigned)(v>>32));
}

__global__ void __launch_bounds__(256) lstm_persist_k(const float* __restrict__ gx,
                                                      const float* __restrict__ Whh,
                                                      float* __restrict__ rnn)
{
    extern __shared__ float sm[];
    float* w_sm    = sm;                       /* [256*32*4]  wT[k4][r] float4 */
    float* h_sm    = sm + 32768;               /* [8*1024]                     */
    float* red_sm  = h_sm + 8192;              /* [8][32][8]                   */
    float* gate_sm = red_sm + 2048;            /* [32][8]                      */

    const int tid = threadIdx.x;
    const int e_base = blockIdx.x*8;
    const int s_w = tid>>5;                    /* warp = K slice  */
    const int r   = tid&31;                    /* lane = gate row */

    /* load Whh rows (transposed) once: thread loop r_row, lane covers k4 */
    for (int rr = 0; rr < 32; rr++){
        long j = (long)((rr>>3)*E_ + e_base + (rr&7));
        const float4* src = (const float4*)(Whh + j*E_);
        for (int k4 = tid; k4 < 256; k4 += 256)
            *(float4*)&w_sm[(k4*32 + rr)*4] = src[k4];
    }

    /* c state in registers of combine threads (tid<64): e=tid&7, b=tid>>3 */
    float c_reg = 0.f;
    const int cb = tid>>3, ce = tid&7;

    __syncthreads();

    int parity = 0;
    for (int step = 0; step < S_; step++){
        /* broadcast h into smem (L2 reads, bypass stale L1) */
        const float4* hsrc = (const float4*)g_hbuf[parity];
        #pragma unroll
        for (int i = tid; i < 2048; i += 256)
            *(float4*)&h_sm[i*4] = __ldcg(hsrc + i);
        __syncthreads();

        /* partial dots: rows r, all batches, k4 in [s_w*32, s_w*32+32) */
        unsigned long long acc0[8], acc1[8];
        #pragma unroll
        for (int b=0;b<8;b++){ acc0[b]=0ull; acc1[b]=0ull; }
        const int k4b = s_w*32;
        #pragma unroll 8
        for (int k4 = k4b; k4 < k4b+32; k4++){
            const unsigned long long* w2 = (const unsigned long long*)&w_sm[(k4*32 + r)*4];
            unsigned long long w01 = w2[0], w23 = w2[1];
            #pragma unroll
            for (int b=0;b<8;b++){
                const unsigned long long* h2p = (const unsigned long long*)&h_sm[b*E_ + k4*4];
                fma2(acc0[b], w01, h2p[0]);
                fma2(acc1[b], w23, h2p[1]);
            }
        }
        #pragma unroll
        for (int b=0;b<8;b++)
            red_sm[s_w*256 + r*8 + b] = f2sum(acc0[b]) + f2sum(acc1[b]);
        __syncthreads();

        /* reduce over 8 slices, add gx: thread (b=tid>>5, rr=tid&31) */
        {
            const int b2 = tid>>5, rr = tid&31;
            long j = (long)((rr>>3)*E_ + e_base + (rr&7));
            float g = gx[(long)step*B_*G4_ + (long)b2*G4_ + j];
            #pragma unroll
            for (int ss=0; ss<8; ss++) g += red_sm[ss*256 + rr*8 + b2];
            gate_sm[rr*8 + b2] = g;
        }
        __syncthreads();

        /* combine gates, update c/h (tid < 64) */
        if (tid < 64){
            float gi = gate_sm[(0*8+ce)*8 + cb];
            float gf = gate_sm[(1*8+ce)*8 + cb];
            float gg = gate_sm[(2*8+ce)*8 + cb];
            float go = gate_sm[(3*8+ce)*8 + cb];
            c_reg = psigm(gf)*c_reg + psigm(gi)*tanhf(gg);
            float h = psigm(go)*tanhf(c_reg);
            int idx = cb*E_ + e_base + ce;
            __stcg(&g_hbuf[parity^1][idx], h);
            rnn[(long)step*B_*E_ + idx] = h;
            __threadfence();
        }
        __syncthreads();

        /* grid barrier (monotonic generation counter) */
        if (tid == 0){
            unsigned gen = g_bar_gen;
            __threadfence();
            if (atomicAdd(&g_bar_cnt, 1u) == LSTM_BLOCKS - 1u){
                g_bar_cnt = 0u;
                __threadfence();
                g_bar_gen = gen + 1u;
            } else {
                while (g_bar_gen == gen) __nanosleep(32);
            }
            __threadfence();
        }
        __syncthreads();
        parity ^= 1;
    }
}

/* ---------------- softmax over rows of length S ------------------------------- */
__global__ void __launch_bounds__(256) softmax_k(float* __restrict__ sc){
    float* p = sc + (long)blockIdx.x*S_;
    int t = threadIdx.x;
    float4 v0 = ((float4*)p)[t], v1 = ((float4*)p)[t+256];
    float mx = fmaxf(fmaxf(fmaxf(v0.x,v0.y),fmaxf(v0.z,v0.w)),
                     fmaxf(fmaxf(v1.x,v1.y),fmaxf(v1.z,v1.w)));
    #pragma unroll
    for (int o=16;o;o>>=1) mx = fmaxf(mx, __shfl_xor_sync(~0u,mx,o));
    __shared__ float sm[8];
    int w=t>>5, l=t&31;
    if (l==0) sm[w]=mx;
    __syncthreads();
    if (t<32){ float a=(l<8)?sm[l]:-1e30f;
        #pragma unroll
        for(int o=4;o;o>>=1) a=fmaxf(a,__shfl_xor_sync(~0u,a,o));
        if(l==0) sm[0]=a; }
    __syncthreads();
    mx = sm[0];
    v0.x=__expf(v0.x-mx); v0.y=__expf(v0.y-mx); v0.z=__expf(v0.z-mx); v0.w=__expf(v0.w-mx);
    v1.x=__expf(v1.x-mx); v1.y=__expf(v1.y-mx); v1.z=__expf(v1.z-mx); v1.w=__expf(v1.w-mx);
    float s = v0.x+v0.y+v0.z+v0.w+v1.x+v1.y+v1.z+v1.w;
    #pragma unroll
    for (int o=16;o;o>>=1) s += __shfl_xor_sync(~0u,s,o);
    __shared__ float s2[8];
    if (l==0) s2[w]=s;
    __syncthreads();
    if (t<32){ float a=(l<8)?s2[l]:0.f;
        #pragma unroll
        for(int o=4;o;o>>=1) a+=__shfl_xor_sync(~0u,a,o);
        if(l==0) s2[0]=a; }
    __syncthreads();
    float inv = 1.0f/s2[0];
    v0.x*=inv; v0.y*=inv; v0.z*=inv; v0.w*=inv;
    v1.x*=inv; v1.y*=inv; v1.z*=inv; v1.w*=inv;
    ((float4*)p)[t]=v0; ((float4*)p)[t+256]=v1;
}

/* ---------------- host side ---------------------------------------------------- */
static float* devp(const void* sym){ void* p=0; cudaGetSymbolAddress(&p,sym); return (float*)p; }

extern "C" void kernel_launch(void* const* d_in, const int* in_sizes, int n_in,
                              void* d_out, int out_size)
{
    const float* inputs = (const float*)d_in[0];
    const float* mask   = (const float*)d_in[1];
    const float* Wih    = (const float*)d_in[3];
    const float* Whh    = (const float*)d_in[4];
    const float* bih    = (const float*)d_in[5];
    const float* bhh    = (const float*)d_in[6];
    const float* lnstart_g=(const float*)d_in[7],  *lnstart_b=(const float*)d_in[8];
    const float* lnmem_g  =(const float*)d_in[9],  *lnmem_b  =(const float*)d_in[10];
    const float* lnmid_g  =(const float*)d_in[11], *lnmid_b  =(const float*)d_in[12];
    const float* lnff_g   =(const float*)d_in[13], *lnff_b   =(const float*)d_in[14];
    const float* lnxff_g  =(const float*)d_in[15], *lnxff_b  =(const float*)d_in[16];
    const float* qln_g    =(const float*)d_in[17], *qln_b    =(const float*)d_in[18];
    const float* qs    = (const float*)d_in[19];
    const float* ks_p  = (const float*)d_in[20];
    const float* vs_p  = (const float*)d_in[21];
    const float* op_W  = (const float*)d_in[22];
    const float* op_b  = (const float*)d_in[23];
    const float* ql_W  = (const float*)d_in[24];
    const float* ql_b  = (const float*)d_in[25];
    const float* boom_W= (const float*)d_in[26];
    const float* boom_b= (const float*)d_in[27];
    float* out = (float*)d_out;

    float *xln=devp(g_xln), *gx=devp(g_gx), *rnn=devp(g_rnn), *mh=devp(g_mh),
          *hmid=devp(g_hmid), *qpre=devp(g_qpre), *query=devp(g_query),
          *qsc=devp(g_qsc), *ksc=devp(g_ksc), *vsc=devp(g_vsc),
          *scores=devp(g_scores), *h2=devp(g_h2), *xff=devp(g_xff),
          *lnffo=devp(g_lnffo), *bsum=devp(g_bias_sum);

    cudaFuncSetAttribute(lstm_persist_k,
                         cudaFuncAttributeMaxDynamicSharedMemorySize, LSTM_SMEM_BYTES);

    /* prep */
    bias_sum_k<<<16,256>>>(bih,bhh);
    vs_proj_k<<<256,256>>>(vs_p,op_W,op_b);
    vs_gate_k<<<4,256>>>();
    zero_state_k<<<32,256>>>();

    /* 1. LN start */
    ln_kernel<<<SB_,256>>>(inputs, xln, lnstart_g, lnstart_b);

    /* 2. gx = xln @ Wih^T + (bih+bhh) */
    gemm_f32<<<dim3(32,128,1),256>>>(xln,Wih,bsum,0, gx, SB_,G4_,E_,
        E_,E_,G4_,0, 0,0,0,0, 1,0,1.0f);

    /* 3. LSTM: one persistent kernel */
    lstm_persist_k<<<LSTM_BLOCKS,256,LSTM_SMEM_BYTES>>>(gx, Whh, rnn);

    /* 4. LNs on rnn output */
    ln_kernel<<<SB_,256>>>(rnn, mh,   lnmem_g, lnmem_b);
    ln_kernel<<<SB_,256>>>(rnn, hmid, lnmid_g, lnmid_b);

    /* 5. query projection + LN + qkv scaling */
    gemm_f32<<<dim3(8,128,1),256>>>(hmid,ql_W,ql_b,0, qpre, SB_,E_,E_,
        E_,E_,E_,0, 0,0,0,0, 1,0,1.0f);
    ln_kernel<<<SB_,256>>>(qpre, query, qln_g, qln_b);
    scale_qkv_k<<<1024,256>>>(qs, ks_p);

    /* 6. scores = q.k/sqrt(E) + mask : batched NT gemm */
    gemm_f32<<<dim3(16,16,8),256>>>(qsc,ksc,0,mask, scores, S_,S_,E_,
        B_*E_, B_*E_, S_, S_, E_, E_, (long)S_*S_, 0, 1,1, 0.03125f);

    /* 7. softmax rows */
    softmax_k<<<B_*S_,256>>>(scores);

    /* 8. mix = w @ v, + hmid residual : batched NN gemm */
    gemm_f32<<<dim3(8,16,8),256>>>(scores,vsc,0,hmid, h2, S_,E_,S_,
        S_, B_*E_, B_*E_, B_*E_, (long)S_*S_, E_, E_, E_, 0,2, 1.0f);

    /* 9. boom: out = gelu(LN_xff(h2)@boom_W^T + b) + LN_ff(h2) */
    ln_kernel<<<SB_,256>>>(h2, xff,   lnxff_g, lnxff_b);
    ln_kernel<<<SB_,256>>>(h2, lnffo, lnff_g,  lnff_b);
    gemm_f32<<<dim3(8,128,1),256>>>(xff,boom_W,boom_b,lnffo, out, SB_,E_,E_,
        E_,E_,E_,E_, 0,0,0,0, 1,3, 1.0f);
}

// round 6
// speedup vs baseline: 1.2149x; 1.2149x over previous
#include <cuda_runtime.h>
#include <math.h>

#define S_  2048
#define B_  8
#define E_  1024
#define SB_ (S_*B_)
#define G4_ (4*E_)

/* ---------------- static device scratch (no runtime allocation) ---------------- */
__device__ float g_bias_sum[G4_];
__device__ float g_xln  [SB_*E_];
__device__ float g_gx   [(size_t)SB_*G4_];      /* 256 MB */
__device__ float g_rnn  [SB_*E_];
__device__ float g_mh   [SB_*E_];
__device__ float g_hmid [SB_*E_];
__device__ float g_qpre [SB_*E_];
__device__ float g_query[SB_*E_];
__device__ float g_qsc  [SB_*E_];
__device__ float g_ksc  [SB_*E_];
__device__ float g_vsc  [SB_*E_];
__device__ float g_scores[(size_t)B_*S_*S_];    /* 128 MB */
__device__ float g_h2   [SB_*E_];
__device__ float g_xff  [SB_*E_];
__device__ float g_lnffo[SB_*E_];
__device__ float g_tbuf [2*E_];
__device__ float g_vsgv [E_];
__device__ float g_hbuf [2][B_*E_];
__device__ unsigned g_bar_cnt;
__device__ volatile unsigned g_bar_gen;

__device__ __forceinline__ float fsigm(float x){ return 1.0f/(1.0f+__expf(-x)); }
__device__ __forceinline__ float psigm(float x){ return 1.0f/(1.0f+expf(-x)); }
__device__ __forceinline__ float to_tf32(float x){
    float r; asm("cvt.rna.tf32.f32 %0, %1;" : "=f"(r) : "f"(x)); return r;
}

/* ---------------- LayerNorm over last dim (E=1024), one block per row ---------- */
__global__ void __launch_bounds__(256) ln_kernel(const float* __restrict__ in,
                                                 float* __restrict__ out,
                                                 const float* __restrict__ gamma,
                                                 const float* __restrict__ beta)
{
    long row = blockIdx.x;
    const float4* x = (const float4*)(in + row*E_);
    int t = threadIdx.x;
    float4 v = x[t];
    float s = v.x+v.y+v.z+v.w;
    float q = v.x*v.x+v.y*v.y+v.z*v.z+v.w*v.w;
    #pragma unroll
    for (int o=16;o;o>>=1){ s += __shfl_xor_sync(~0u,s,o); q += __shfl_xor_sync(~0u,q,o); }
    __shared__ float ss[8], sq[8];
    int w = t>>5, l = t&31;
    if (l==0){ ss[w]=s; sq[w]=q; }
    __syncthreads();
    if (t<32){
        float a = (l<8)? ss[l]:0.f, b = (l<8)? sq[l]:0.f;
        #pragma unroll
        for (int o=4;o;o>>=1){ a += __shfl_xor_sync(~0u,a,o); b += __shfl_xor_sync(~0u,b,o); }
        if (l==0){ ss[0]=a; sq[0]=b; }
    }
    __syncthreads();
    float mean = ss[0]*(1.0f/E_);
    float var  = sq[0]*(1.0f/E_) - mean*mean;
    float inv  = rsqrtf(fmaxf(var,0.f)+1e-12f);
    float4 g = ((const float4*)gamma)[t];
    float4 b = ((const float4*)beta)[t];
    float4 o;
    o.x=(v.x-mean)*inv*g.x+b.x; o.y=(v.y-mean)*inv*g.y+b.y;
    o.z=(v.z-mean)*inv*g.z+b.z; o.w=(v.w-mean)*inv*g.w+b.w;
    ((float4*)(out + row*E_))[t] = o;
}

/* ---------------- fp32 GEMM (kept for gx: feeds the recurrence) ---------------- */
__global__ void __launch_bounds__(256) gemm_f32(
    const float* __restrict__ A, const float* __restrict__ B,
    const float* __restrict__ bias, float* __restrict__ C,
    int M, int N, int K, int lda, int ldb, int ldc)
{
    __shared__ float As[8][128];
    __shared__ float Bs[8][128];
    const int tid = threadIdx.x;
    const int m0 = blockIdx.y*128, n0 = blockIdx.x*128;
    const int lr = tid>>1, lk = (tid&1)*4;
    const int tx = tid&15, ty = tid>>4;

    float acc[8][8];
    #pragma unroll
    for (int i=0;i<8;i++)
        #pragma unroll
        for (int j=0;j<8;j++) acc[i][j]=0.f;

    float4 ar = *(const float4*)(A + (long)(m0+lr)*lda + lk);
    float4 br = *(const float4*)(B + (long)(n0+lr)*ldb + lk);

    for (int k0=0;k0<K;k0+=8){
        As[lk+0][lr]=ar.x; As[lk+1][lr]=ar.y; As[lk+2][lr]=ar.z; As[lk+3][lr]=ar.w;
        Bs[lk+0][lr]=br.x; Bs[lk+1][lr]=br.y; Bs[lk+2][lr]=br.z; Bs[lk+3][lr]=br.w;
        __syncthreads();
        if (k0+8 < K){
            ar = *(const float4*)(A + (long)(m0+lr)*lda + k0+8+lk);
            br = *(const float4*)(B + (long)(n0+lr)*ldb + k0+8+lk);
        }
        #pragma unroll
        for (int kk=0;kk<8;kk++){
            float af[8], bf[8];
            *(float4*)(af)   = *(const float4*)&As[kk][ty*8];
            *(float4*)(af+4) = *(const float4*)&As[kk][ty*8+4];
            *(float4*)(bf)   = *(const float4*)&Bs[kk][tx*8];
            *(float4*)(bf+4) = *(const float4*)&Bs[kk][tx*8+4];
            #pragma unroll
            for (int i=0;i<8;i++)
                #pragma unroll
                for (int j=0;j<8;j++) acc[i][j] = fmaf(af[i], bf[j], acc[i][j]);
        }
        __syncthreads();
    }
    #pragma unroll
    for (int i=0;i<8;i++){
        long m = m0 + ty*8 + i;
        #pragma unroll
        for (int j=0;j<8;j+=4){
            long n = n0 + tx*8 + j;
            float4 o;
            o.x=acc[i][j+0]+bias[n+0]; o.y=acc[i][j+1]+bias[n+1];
            o.z=acc[i][j+2]+bias[n+2]; o.w=acc[i][j+3]+bias[n+3];
            *(float4*)(C + m*ldc + n) = o;
        }
    }
}

/* ---------------- tf32 tensor-core GEMM 128x128x16, mma.m16n8k8 ----------------
   8 warps (4m x 2n), warp tile 32x64.  bT=1: B is [N,K] (B^T).  bT=0: B is [K,N].
   mode 0: acc + bias[n]
   mode 1: acc*alpha + extra[m,n]; causal: tile n0>m0 fully masked -> copy extra
   mode 2: acc + extra[m,n];       causal: K limited to m0+128 (w==0 beyond)
   mode 3: gelu(acc+bias[n]) + extra[m,n]                                        */
__global__ void __launch_bounds__(256) gemm_tf32(
    const float* __restrict__ A, const float* __restrict__ B,
    const float* __restrict__ bias, const float* __restrict__ extra,
    float* __restrict__ C, int M, int N, int K,
    int lda, int ldb, int ldc, int ldx,
    long sA, long sB, long sC, long sX, int bT, int mode, float alpha, int causal)
{
    __shared__ float As[128][20];
    __shared__ float Bs[16][136];
    A += (long)blockIdx.z * sA;
    B += (long)blockIdx.z * sB;
    C += (long)blockIdx.z * sC;
    if (extra) extra += (long)blockIdx.z * sX;
    const int tid = threadIdx.x;
    const int m0 = blockIdx.y*128, n0 = blockIdx.x*128;

    /* fully-masked score tile: output = mask (softmax gives exact 0 there) */
    if (mode==1 && causal && n0 > m0){
        for (int idx = tid; idx < 128*32; idx += 256){
            int r = idx>>5, c4 = (idx&31)*4;
            *(float4*)(C + (long)(m0+r)*ldc + n0+c4) =
                *(const float4*)(extra + (long)(m0+r)*ldx + n0+c4);
        }
        return;
    }
    const int Keff = (mode==2 && causal && m0+128 < K) ? m0+128 : K;

    const int lane = tid&31, wid = tid>>5;
    const int g = lane>>2, tig = lane&3;
    const int wm = wid&3, wn = wid>>2;
    const int arow = tid>>1, acol = (tid&1)*8;      /* A / B(NT) loader coords */

    float c[2][8][4];
    #pragma unroll
    for (int mt=0;mt<2;mt++)
        #pragma unroll
        for (int nt=0;nt<8;nt++)
            #pragma unroll
            for (int i=0;i<4;i++) c[mt][nt][i]=0.f;

    float4 pa0, pa1, pb0, pb1;
    pa0 = *(const float4*)(A + (long)(m0+arow)*lda + acol);
    pa1 = *(const float4*)(A + (long)(m0+arow)*lda + acol+4);
    if (bT){
        pb0 = *(const float4*)(B + (long)(n0+arow)*ldb + acol);
        pb1 = *(const float4*)(B + (long)(n0+arow)*ldb + acol+4);
    } else {
        pb0 = *(const float4*)(B + (long)(tid>>5)*ldb + n0 + (tid&31)*4);
        pb1 = *(const float4*)(B + (long)((tid>>5)+8)*ldb + n0 + (tid&31)*4);
    }

    for (int k0=0; k0<Keff; k0+=16){
        /* ---- store tiles (converted to tf32) ---- */
        {
            float* d0 = &As[arow][acol];
            d0[0]=to_tf32(pa0.x); d0[1]=to_tf32(pa0.y); d0[2]=to_tf32(pa0.z); d0[3]=to_tf32(pa0.w);
            d0[4]=to_tf32(pa1.x); d0[5]=to_tf32(pa1.y); d0[6]=to_tf32(pa1.z); d0[7]=to_tf32(pa1.w);
        }
        if (bT){
            Bs[acol+0][arow]=to_tf32(pb0.x); Bs[acol+1][arow]=to_tf32(pb0.y);
            Bs[acol+2][arow]=to_tf32(pb0.z); Bs[acol+3][arow]=to_tf32(pb0.w);
            Bs[acol+4][arow]=to_tf32(pb1.x); Bs[acol+5][arow]=to_tf32(pb1.y);
            Bs[acol+6][arow]=to_tf32(pb1.z); Bs[acol+7][arow]=to_tf32(pb1.w);
        } else {
            int kr = tid>>5, nc = (tid&31)*4;
            float* d0 = &Bs[kr][nc];
            d0[0]=to_tf32(pb0.x); d0[1]=to_tf32(pb0.y); d0[2]=to_tf32(pb0.z); d0[3]=to_tf32(pb0.w);
            float* d1 = &Bs[kr+8][nc];
            d1[0]=to_tf32(pb1.x); d1[1]=to_tf32(pb1.y); d1[2]=to_tf32(pb1.z); d1[3]=to_tf32(pb1.w);
        }
        __syncthreads();

        /* ---- prefetch next tile ---- */
        if (k0+16 < Keff){
            pa0 = *(const float4*)(A + (long)(m0+arow)*lda + k0+16+acol);
            pa1 = *(const float4*)(A + (long)(m0+arow)*lda + k0+16+acol+4);
            if (bT){
                pb0 = *(const float4*)(B + (long)(n0+arow)*ldb + k0+16+acol);
                pb1 = *(const float4*)(B + (long)(n0+arow)*ldb + k0+16+acol+4);
            } else {
                pb0 = *(const float4*)(B + (long)(k0+16+(tid>>5))*ldb + n0 + (tid&31)*4);
                pb1 = *(const float4*)(B + (long)(k0+24+(tid>>5))*ldb + n0 + (tid&31)*4);
            }
        }

        /* ---- compute 2 k-steps of 8 ---- */
        #pragma unroll
        for (int kk=0; kk<16; kk+=8){
            unsigned a[2][4], b[8][2];
            #pragma unroll
            for (int mt=0;mt<2;mt++){
                const float* p = &As[wm*32 + mt*16 + g][kk+tig];
                a[mt][0]=__float_as_uint(p[0]);
                a[mt][1]=__float_as_uint(p[8*20]);
                a[mt][2]=__float_as_uint(p[4]);
                a[mt][3]=__float_as_uint(p[8*20+4]);
            }
            #pragma unroll
            for (int nt=0;nt<8;nt++){
                const float* p = &Bs[kk+tig][wn*64 + nt*8 + g];
                b[nt][0]=__float_as_uint(p[0]);
                b[nt][1]=__float_as_uint(p[4*136]);
            }
            #pragma unroll
            for (int mt=0;mt<2;mt++)
                #pragma unroll
                for (int nt=0;nt<8;nt++)
                    asm volatile(
                        "mma.sync.aligned.m16n8k8.row.col.f32.tf32.tf32.f32 "
                        "{%0,%1,%2,%3}, {%4,%5,%6,%7}, {%8,%9}, {%0,%1,%2,%3};\n"
                        : "+f"(c[mt][nt][0]), "+f"(c[mt][nt][1]),
                          "+f"(c[mt][nt][2]), "+f"(c[mt][nt][3])
                        : "r"(a[mt][0]),"r"(a[mt][1]),"r"(a[mt][2]),"r"(a[mt][3]),
                          "r"(b[nt][0]),"r"(b[nt][1]));
        }
        __syncthreads();
    }

    /* ---- epilogue ---- */
    #pragma unroll
    for (int mt=0;mt<2;mt++){
        long r0 = m0 + wm*32 + mt*16 + g;
        long r1 = r0 + 8;
        #pragma unroll
        for (int nt=0;nt<8;nt++){
            long n = n0 + wn*64 + nt*8 + 2*tig;
            float v0=c[mt][nt][0]*alpha, v1=c[mt][nt][1]*alpha;
            float v2=c[mt][nt][2]*alpha, v3=c[mt][nt][3]*alpha;
            if (mode==0 || mode==3){
                float b0=bias[n], b1=bias[n+1];
                v0+=b0; v1+=b1; v2+=b0; v3+=b1;
            }
            if (mode==3){
                v0 = v0*fsigm(1.702f*v0); v1 = v1*fsigm(1.702f*v1);
                v2 = v2*fsigm(1.702f*v2); v3 = v3*fsigm(1.702f*v3);
            }
            if (mode==1 || mode==2 || mode==3){
                v0 += extra[r0*ldx+n]; v1 += extra[r0*ldx+n+1];
                v2 += extra[r1*ldx+n]; v3 += extra[r1*ldx+n+1];
            }
            float2 lo = {v0,v1}, hi = {v2,v3};
            *(float2*)(C + r0*ldc + n) = lo;
            *(float2*)(C + r1*ldc + n) = hi;
        }
    }
}

/* ---------------- small prep kernels ------------------------------------------ */
__global__ void bias_sum_k(const float* __restrict__ a, const float* __restrict__ b){
    int i = blockIdx.x*256 + threadIdx.x;
    if (i < G4_) g_bias_sum[i] = a[i] + b[i];
}
__global__ void __launch_bounds__(256) vs_proj_k(const float* __restrict__ vs_p,
                                                 const float* __restrict__ op_W,
                                                 const float* __restrict__ op_b){
    int j = blockIdx.x*8 + (threadIdx.x>>5);
    int l = threadIdx.x & 31;
    const float* w = op_W + (long)j*E_;
    float acc = 0.f;
    for (int k=l; k<E_; k+=32) acc += psigm(vs_p[k]) * w[k];
    #pragma unroll
    for (int o=16;o;o>>=1) acc += __shfl_xor_sync(~0u,acc,o);
    if (l==0) g_tbuf[j] = acc + op_b[j];
}
__global__ void vs_gate_k(){
    int e = blockIdx.x*256 + threadIdx.x;
    if (e < E_) g_vsgv[e] = psigm(g_tbuf[E_+e]) * tanhf(g_tbuf[e]);
}
__global__ void zero_state_k(){
    int i = blockIdx.x*256 + threadIdx.x;
    if (i < B_*E_){ g_hbuf[0][i] = 0.f; g_hbuf[1][i] = 0.f; }
}
__global__ void scale_qkv_k(const float* __restrict__ qs, const float* __restrict__ ks){
    for (long i = (long)blockIdx.x*blockDim.x + threadIdx.x; i < (long)SB_*E_;
         i += (long)gridDim.x*blockDim.x){
        int e = (int)(i & (E_-1));
        g_qsc[i] = fsigm(qs[e]) * g_query[i];
        float m = g_mh[i];
        g_ksc[i] = fsigm(ks[e]) * m;
        g_vsc[i] = g_vsgv[e] * m;
    }
}

/* ---------------- persistent LSTM: 128 blocks x 256 threads -------------------- */
#define LSTM_BLOCKS 128
#define LSTM_SMEM_BYTES (131072 + 32768 + 8192 + 1024 + 256)

__device__ __forceinline__ void fma2(unsigned long long &acc,
                                     unsigned long long a, unsigned long long b){
    asm("fma.rn.f32x2 %0, %1, %2, %0;" : "+l"(acc) : "l"(a), "l"(b));
}
__device__ __forceinline__ float f2sum(unsigned long long v){
    return __uint_as_float((unsigned)v) + __uint_as_float((unsigned)(v>>32));
}

__global__ void __launch_bounds__(256) lstm_persist_k(const float* __restrict__ gx,
                                                      const float* __restrict__ Whh,
                                                      float* __restrict__ rnn)
{
    extern __shared__ float sm[];
    float* w_sm    = sm;                       /* [256*32*4]  wT[k4][r] float4 */
    float* h_sm    = sm + 32768;               /* [8*1024]                     */
    float* red_sm  = h_sm + 8192;              /* [8][32][8]                   */
    float* gate_sm = red_sm + 2048;            /* [32][8]                      */

    const int tid = threadIdx.x;
    const int e_base = blockIdx.x*8;
    const int s_w = tid>>5;
    const int r   = tid&31;

    for (int rr = 0; rr < 32; rr++){
        long j = (long)((rr>>3)*E_ + e_base + (rr&7));
        const float4* src = (const float4*)(Whh + j*E_);
        for (int k4 = tid; k4 < 256; k4 += 256)
            *(float4*)&w_sm[(k4*32 + rr)*4] = src[k4];
    }

    float c_reg = 0.f;
    const int cb = tid>>3, ce = tid&7;

    __syncthreads();

    int parity = 0;
    for (int step = 0; step < S_; step++){
        const float4* hsrc = (const float4*)g_hbuf[parity];
        #pragma unroll
        for (int i = tid; i < 2048; i += 256)
            *(float4*)&h_sm[i*4] = __ldcg(hsrc + i);
        __syncthreads();

        unsigned long long acc0[8], acc1[8];
        #pragma unroll
        for (int b=0;b<8;b++){ acc0[b]=0ull; acc1[b]=0ull; }
        const int k4b = s_w*32;
        #pragma unroll 8
        for (int k4 = k4b; k4 < k4b+32; k4++){
            const unsigned long long* w2 = (const unsigned long long*)&w_sm[(k4*32 + r)*4];
            unsigned long long w01 = w2[0], w23 = w2[1];
            #pragma unroll
            for (int b=0;b<8;b++){
                const unsigned long long* h2p = (const unsigned long long*)&h_sm[b*E_ + k4*4];
                fma2(acc0[b], w01, h2p[0]);
                fma2(acc1[b], w23, h2p[1]);
            }
        }
        #pragma unroll
        for (int b=0;b<8;b++)
            red_sm[s_w*256 + r*8 + b] = f2sum(acc0[b]) + f2sum(acc1[b]);
        __syncthreads();

        {
            const int b2 = tid>>5, rr = tid&31;
            long j = (long)((rr>>3)*E_ + e_base + (rr&7));
            float g = gx[(long)step*B_*G4_ + (long)b2*G4_ + j];
            #pragma unroll
            for (int ss=0; ss<8; ss++) g += red_sm[ss*256 + rr*8 + b2];
            gate_sm[rr*8 + b2] = g;
        }
        __syncthreads();

        if (tid < 64){
            float gi = gate_sm[(0*8+ce)*8 + cb];
            float gf = gate_sm[(1*8+ce)*8 + cb];
            float gg = gate_sm[(2*8+ce)*8 + cb];
            float go = gate_sm[(3*8+ce)*8 + cb];
            c_reg = psigm(gf)*c_reg + psigm(gi)*tanhf(gg);
            float h = psigm(go)*tanhf(c_reg);
            int idx = cb*E_ + e_base + ce;
            __stcg(&g_hbuf[parity^1][idx], h);
            rnn[(long)step*B_*E_ + idx] = h;
            __threadfence();
        }
        __syncthreads();

        if (tid == 0){
            unsigned gen = g_bar_gen;
            __threadfence();
            if (atomicAdd(&g_bar_cnt, 1u) == LSTM_BLOCKS - 1u){
                g_bar_cnt = 0u;
                __threadfence();
                g_bar_gen = gen + 1u;
            } else {
                while (g_bar_gen == gen) __nanosleep(32);
            }
            __threadfence();
        }
        __syncthreads();
        parity ^= 1;
    }
}

/* ---------------- softmax over rows of length S ------------------------------- */
__global__ void __launch_bounds__(256) softmax_k(float* __restrict__ sc){
    float* p = sc + (long)blockIdx.x*S_;
    int t = threadIdx.x;
    float4 v0 = ((float4*)p)[t], v1 = ((float4*)p)[t+256];
    float mx = fmaxf(fmaxf(fmaxf(v0.x,v0.y),fmaxf(v0.z,v0.w)),
                     fmaxf(fmaxf(v1.x,v1.y),fmaxf(v1.z,v1.w)));
    #pragma unroll
    for (int o=16;o;o>>=1) mx = fmaxf(mx, __shfl_xor_sync(~0u,mx,o));
    __shared__ float sm[8];
    int w=t>>5, l=t&31;
    if (l==0) sm[w]=mx;
    __syncthreads();
    if (t<32){ float a=(l<8)?sm[l]:-1e30f;
        #pragma unroll
        for(int o=4;o;o>>=1) a=fmaxf(a,__shfl_xor_sync(~0u,a,o));
        if(l==0) sm[0]=a; }
    __syncthreads();
    mx = sm[0];
    v0.x=__expf(v0.x-mx); v0.y=__expf(v0.y-mx); v0.z=__expf(v0.z-mx); v0.w=__expf(v0.w-mx);
    v1.x=__expf(v1.x-mx); v1.y=__expf(v1.y-mx); v1.z=__expf(v1.z-mx); v1.w=__expf(v1.w-mx);
    float s = v0.x+v0.y+v0.z+v0.w+v1.x+v1.y+v1.z+v1.w;
    #pragma unroll
    for (int o=16;o;o>>=1) s += __shfl_xor_sync(~0u,s,o);
    __shared__ float s2[8];
    if (l==0) s2[w]=s;
    __syncthreads();
    if (t<32){ float a=(l<8)?s2[l]:0.f;
        #pragma unroll
        for(int o=4;o;o>>=1) a+=__shfl_xor_sync(~0u,a,o);
        if(l==0) s2[0]=a; }
    __syncthreads();
    float inv = 1.0f/s2[0];
    v0.x*=inv; v0.y*=inv; v0.z*=inv; v0.w*=inv;
    v1.x*=inv; v1.y*=inv; v1.z*=inv; v1.w*=inv;
    ((float4*)p)[t]=v0; ((float4*)p)[t+256]=v1;
}

/* ---------------- host side ---------------------------------------------------- */
static float* devp(const void* sym){ void* p=0; cudaGetSymbolAddress(&p,sym); return (float*)p; }

extern "C" void kernel_launch(void* const* d_in, const int* in_sizes, int n_in,
                              void* d_out, int out_size)
{
    const float* inputs = (const float*)d_in[0];
    const float* mask   = (const float*)d_in[1];
    const float* Wih    = (const float*)d_in[3];
    const float* Whh    = (const float*)d_in[4];
    const float* bih    = (const float*)d_in[5];
    const float* bhh    = (const float*)d_in[6];
    const float* lnstart_g=(const float*)d_in[7],  *lnstart_b=(const float*)d_in[8];
    const float* lnmem_g  =(const float*)d_in[9],  *lnmem_b  =(const float*)d_in[10];
    const float* lnmid_g  =(const float*)d_in[11], *lnmid_b  =(const float*)d_in[12];
    const float* lnff_g   =(const float*)d_in[13], *lnff_b   =(const float*)d_in[14];
    const float* lnxff_g  =(const float*)d_in[15], *lnxff_b  =(const float*)d_in[16];
    const float* qln_g    =(const float*)d_in[17], *qln_b    =(const float*)d_in[18];
    const float* qs    = (const float*)d_in[19];
    const float* ks_p  = (const float*)d_in[20];
    const float* vs_p  = (const float*)d_in[21];
    const float* op_W  = (const float*)d_in[22];
    const float* op_b  = (const float*)d_in[23];
    const float* ql_W  = (const float*)d_in[24];
    const float* ql_b  = (const float*)d_in[25];
    const float* boom_W= (const float*)d_in[26];
    const float* boom_b= (const float*)d_in[27];
    float* out = (float*)d_out;

    float *xln=devp(g_xln), *gx=devp(g_gx), *rnn=devp(g_rnn), *mh=devp(g_mh),
          *hmid=devp(g_hmid), *qpre=devp(g_qpre), *query=devp(g_query),
          *qsc=devp(g_qsc), *ksc=devp(g_ksc), *vsc=devp(g_vsc),
          *scores=devp(g_scores), *h2=devp(g_h2), *xff=devp(g_xff),
          *lnffo=devp(g_lnffo), *bsum=devp(g_bias_sum);

    cudaFuncSetAttribute(lstm_persist_k,
                         cudaFuncAttributeMaxDynamicSharedMemorySize, LSTM_SMEM_BYTES);

    /* prep */
    bias_sum_k<<<16,256>>>(bih,bhh);
    vs_proj_k<<<256,256>>>(vs_p,op_W,op_b);
    vs_gate_k<<<4,256>>>();
    zero_state_k<<<32,256>>>();

    /* 1. LN start */
    ln_kernel<<<SB_,256>>>(inputs, xln, lnstart_g, lnstart_b);

    /* 2. gx = xln @ Wih^T + (bih+bhh) : fp32 (feeds 2048-step recurrence) */
    gemm_f32<<<dim3(32,128,1),256>>>(xln,Wih,bsum, gx, SB_,G4_,E_, E_,E_,G4_);

    /* 3. LSTM: one persistent kernel */
    lstm_persist_k<<<LSTM_BLOCKS,256,LSTM_SMEM_BYTES>>>(gx, Whh, rnn);

    /* 4. LNs on rnn output */
    ln_kernel<<<SB_,256>>>(rnn, mh,   lnmem_g, lnmem_b);
    ln_kernel<<<SB_,256>>>(rnn, hmid, lnmid_g, lnmid_b);

    /* 5. query projection (tf32) + LN + qkv scaling */
    gemm_tf32<<<dim3(8,128,1),256>>>(hmid,ql_W,ql_b,0, qpre, SB_,E_,E_,
        E_,E_,E_,0, 0,0,0,0, 1,0, 1.0f, 0);
    ln_kernel<<<SB_,256>>>(qpre, query, qln_g, qln_b);
    scale_qkv_k<<<1024,256>>>(qs, ks_p);

    /* 6. scores = q.k/sqrt(E) + mask : batched NT tf32, causal-skip */
    gemm_tf32<<<dim3(16,16,8),256>>>(qsc,ksc,0,mask, scores, S_,S_,E_,
        B_*E_, B_*E_, S_, S_, E_, E_, (long)S_*S_, 0, 1,1, 0.03125f, 1);

    /* 7. softmax rows */
    softmax_k<<<B_*S_,256>>>(scores);

    /* 8. mix = w @ v + hmid : batched NN tf32, causal K-limit */
    gemm_tf32<<<dim3(8,16,8),256>>>(scores,vsc,0,hmid, h2, S_,E_,S_,
        S_, B_*E_, B_*E_, B_*E_, (long)S_*S_, E_, E_, E_, 0,2, 1.0f, 1);

    /* 9. boom: out = gelu(LN_xff(h2)@boom_W^T + b) + LN_ff(h2) : tf32 */
    ln_kernel<<<SB_,256>>>(h2, xff,   lnxff_g, lnxff_b);
    ln_kernel<<<SB_,256>>>(h2, lnffo, lnff_g,  lnff_b);
    gemm_tf32<<<dim3(8,128,1),256>>>(xff,boom_W,boom_b,lnffo, out, SB_,E_,E_,
        E_,E_,E_,E_, 0,0,0,0, 1,3, 1.0f, 0);
}

// round 11
// speedup vs baseline: 1.4622x; 1.2036x over previous
#include <cuda_runtime.h>
#include <cuda_fp16.h>
#include <math.h>
#include <cstdint>

#define S_  2048
#define B_  8
#define E_  1024
#define SB_ (S_*B_)
#define G4_ (4*E_)

/* ---------------- static device scratch (no runtime allocation) ---------------- */
__device__ float g_bias_sum[G4_];
__device__ float g_xln  [SB_*E_];
__device__ float g_gx   [(size_t)SB_*G4_];
__device__ float g_rnn  [SB_*E_];
__device__ float g_mh   [SB_*E_];
__device__ float g_hmid [SB_*E_];
__device__ float g_qpre [SB_*E_];
__device__ float g_query[SB_*E_];
__device__ float g_scores[(size_t)B_*S_*S_];
__device__ float g_h2   [SB_*E_];
__device__ float g_xff  [SB_*E_];
__device__ float g_lnffo[SB_*E_];
__device__ float g_tbuf [2*E_];
__device__ float g_vsgv [E_];
__device__ float g_hbuf [2][B_*E_];
__device__ unsigned g_bar_cnt;
__device__ volatile unsigned g_bar_gen;

/* fp16 mirrors for tensor-core GEMM inputs */
__device__ __half gh_xln [SB_*E_];
__device__ __half gh_Wih [(size_t)G4_*E_];
__device__ __half gh_hmid[SB_*E_];
__device__ __half gh_qlW [(size_t)E_*E_];
__device__ __half gh_qsc [SB_*E_];
__device__ __half gh_ksc [SB_*E_];
__device__ __half gh_vT  [(size_t)B_*E_*S_];
__device__ __half gh_sc  [(size_t)B_*S_*S_];
__device__ __half gh_xff [SB_*E_];
__device__ __half gh_bmW [(size_t)E_*E_];

__device__ __forceinline__ float fsigm(float x){ return 1.0f/(1.0f+__expf(-x)); }
__device__ __forceinline__ float psigm(float x){ return 1.0f/(1.0f+expf(-x)); }
__device__ __forceinline__ uint32_t s2u(const void* p){
    return (uint32_t)__cvta_generic_to_shared(p);
}
#define CP_A16(dst, src) \
    asm volatile("cp.async.cg.shared.global [%0], [%1], 16;" :: "r"(dst), "l"(src))
#define CP_COMMIT() asm volatile("cp.async.commit_group;" ::: "memory")
#define CP_WAIT1()  asm volatile("cp.async.wait_group 1;" ::: "memory")
#define CP_WAIT0()  asm volatile("cp.async.wait_group 0;" ::: "memory")
#define LDSM_X4(r0,r1,r2,r3,addr) \
    asm volatile("ldmatrix.sync.aligned.m8n8.x4.shared.b16 {%0,%1,%2,%3}, [%4];" \
        : "=r"(r0), "=r"(r1), "=r"(r2), "=r"(r3) : "r"(addr))
#define MMA_F16(c, a, b0, b1) \
    asm volatile("mma.sync.aligned.m16n8k16.row.col.f32.f16.f16.f32 " \
        "{%0,%1,%2,%3}, {%4,%5,%6,%7}, {%8,%9}, {%0,%1,%2,%3};" \
        : "+f"((c)[0]), "+f"((c)[1]), "+f"((c)[2]), "+f"((c)[3]) \
        : "r"((a)[0]), "r"((a)[1]), "r"((a)[2]), "r"((a)[3]), "r"(b0), "r"(b1))

/* ---------------- fp16 tensor-core GEMM 128x128, K-tile 32, cp.async x2 --------
   NT: A[M,K] lda, B[N,K] ldb, half inputs, fp32 out.  Batched via blockIdx.z.
   mode 0: acc + bias[n]
   mode 1: acc*alpha + extra[m,n]; causal: tile n0>m0 -> copy extra (mask)
   mode 2: acc + extra[m,n];       causal: K limited to m0+128
   mode 3: gelu(acc+bias[n]) + extra[m,n]                                        */
#define LDH 40
__global__ void __launch_bounds__(256) gemm_h(
    const __half* __restrict__ A, const __half* __restrict__ B,
    const float* __restrict__ bias, const float* __restrict__ extra,
    float* __restrict__ C, int K, int lda, int ldb, int ldc, int ldx,
    long sA, long sB, long sC, long sX, int mode, float alpha, int causal)
{
    __shared__ __half As[2][128*LDH];
    __shared__ __half Bs[2][128*LDH];
    const int tid = threadIdx.x, lane = tid&31, wid = tid>>5;
    const int m0 = blockIdx.y*128, n0 = blockIdx.x*128;
    A += (long)blockIdx.z*sA; B += (long)blockIdx.z*sB; C += (long)blockIdx.z*sC;
    if (extra) extra += (long)blockIdx.z*sX;

    if (mode==1 && causal && n0 > m0){
        for (int idx = tid; idx < 128*32; idx += 256){
            int r = idx>>5, c4 = (idx&31)*4;
            *(float4*)(C + (long)(m0+r)*ldc + n0+c4) =
                *(const float4*)(extra + (long)(m0+r)*ldx + n0+c4);
        }
        return;
    }
    const int Keff = (mode==2 && causal && m0+128 < K) ? m0+128 : K;

    const int g = lane>>2, tig = lane&3;
    const int wm = wid&3, wn = wid>>2;
    const int lrow = tid>>1, lseg = tid&1;

    /* loader smem dsts (bytes) */
    uint32_t dA[2], dB[2];
    dA[0] = s2u(&As[0][lrow*LDH + lseg*16]);
    dA[1] = s2u(&As[1][lrow*LDH + lseg*16]);
    dB[0] = s2u(&Bs[0][lrow*LDH + lseg*16]);
    dB[1] = s2u(&Bs[1][lrow*LDH + lseg*16]);
    const __half* srcA = A + (long)(m0+lrow)*lda + lseg*16;
    const __half* srcB = B + (long)(n0+lrow)*ldb + lseg*16;

    /* ldmatrix smem addrs (bytes) */
    const int ar = wm*32 + (lane&15), ac = (lane>>4)<<3;
    const int br = wn*64 + (lane&7) + ((lane>>4)<<3), bc = ((lane>>3)&1)<<3;
    uint32_t aAd[2][2], bAd[2][4];
    #pragma unroll
    for (int bb=0;bb<2;bb++){
        #pragma unroll
        for (int mt=0;mt<2;mt++) aAd[bb][mt] = s2u(&As[bb][(ar+mt*16)*LDH + ac]);
        #pragma unroll
        for (int p=0;p<4;p++)    bAd[bb][p]  = s2u(&Bs[bb][(br+p*16)*LDH + bc]);
    }

    float c[2][8][4];
    #pragma unroll
    for (int mt=0;mt<2;mt++)
        #pragma unroll
        for (int nt=0;nt<8;nt++)
            #pragma unroll
            for (int i=0;i<4;i++) c[mt][nt][i]=0.f;

    const int ntile = Keff/32;
    /* preload tile 0 */
    CP_A16(dA[0],    srcA);      CP_A16(dA[0]+16, srcA+8);
    CP_A16(dB[0],    srcB);      CP_A16(dB[0]+16, srcB+8);
    CP_COMMIT();

    for (int ch=0; ch<ntile; ch++){
        const int buf = ch&1;
        if (ch+1 < ntile){
            const int k1 = (ch+1)*32, b1 = (ch+1)&1;
            CP_A16(dA[b1],    srcA+k1);   CP_A16(dA[b1]+16, srcA+k1+8);
            CP_A16(dB[b1],    srcB+k1);   CP_A16(dB[b1]+16, srcB+k1+8);
            CP_COMMIT();
            CP_WAIT1();
        } else {
            CP_WAIT0();
        }
        __syncthreads();

        #pragma unroll
        for (int kk=0; kk<2; kk++){
            const uint32_t ko = kk*32;   /* 16 halfs = 32 bytes */
            uint32_t a[2][4], b[4][4];
            #pragma unroll
            for (int mt=0;mt<2;mt++)
                LDSM_X4(a[mt][0],a[mt][1],a[mt][2],a[mt][3], aAd[buf][mt]+ko);
            #pragma unroll
            for (int p=0;p<4;p++)
                LDSM_X4(b[p][0],b[p][1],b[p][2],b[p][3], bAd[buf][p]+ko);
            #pragma unroll
            for (int mt=0;mt<2;mt++)
                #pragma unroll
                for (int nt=0;nt<8;nt++){
                    const int p = nt>>1, o = (nt&1)*2;
                    MMA_F16(c[mt][nt], a[mt], b[p][o], b[p][o+1]);
                }
        }
        __syncthreads();
    }

    /* epilogue: direct stores (frag layout: rows g/g+8, cols 2tig) */
    #pragma unroll
    for (int mt=0;mt<2;mt++){
        long r0 = m0 + wm*32 + mt*16 + g;
        long r1 = r0 + 8;
        #pragma unroll
        for (int nt=0;nt<8;nt++){
            long n = n0 + wn*64 + nt*8 + 2*tig;
            float v0=c[mt][nt][0]*alpha, v1=c[mt][nt][1]*alpha;
            float v2=c[mt][nt][2]*alpha, v3=c[mt][nt][3]*alpha;
            if (mode==0 || mode==3){
                float b0=bias[n], b1=bias[n+1];
                v0+=b0; v1+=b1; v2+=b0; v3+=b1;
            }
            if (mode==3){
                v0 = v0*fsigm(1.702f*v0); v1 = v1*fsigm(1.702f*v1);
                v2 = v2*fsigm(1.702f*v2); v3 = v3*fsigm(1.702f*v3);
            }
            if (mode==1 || mode==2 || mode==3){
                v0 += extra[r0*ldx+n]; v1 += extra[r0*ldx+n+1];
                v2 += extra[r1*ldx+n]; v3 += extra[r1*ldx+n+1];
            }
            float2 lo = {v0,v1}, hi = {v2,v3};
            *(float2*)(C + r0*ldc + n) = lo;
            *(float2*)(C + r1*ldc + n) = hi;
        }
    }
}

/* ---------------- f32 -> f16 convert (16B vectorized) -------------------------- */
struct H2x4 { __half2 a, b, c, d; };
__global__ void __launch_bounds__(256) cvt_h_k(const float* __restrict__ in,
                                               __half* __restrict__ out, long n){
    for (long i = ((long)blockIdx.x*blockDim.x + threadIdx.x)*8; i < n;
         i += (long)gridDim.x*blockDim.x*8){
        float4 a = *(const float4*)(in+i);
        float4 b = *(const float4*)(in+i+4);
        H2x4 o;
        o.a = __floats2half2_rn(a.x,a.y);
        o.b = __floats2half2_rn(a.z,a.w);
        o.c = __floats2half2_rn(b.x,b.y);
        o.d = __floats2half2_rn(b.z,b.w);
        *(H2x4*)(out+i) = o;
    }
}

/* ---------------- LayerNorm over last dim (E=1024), one block per row ---------- */
__global__ void __launch_bounds__(256) ln_kernel(const float* __restrict__ in,
                                                 float* __restrict__ out,
                                                 const float* __restrict__ gamma,
                                                 const float* __restrict__ beta)
{
    long row = blockIdx.x;
    const float4* x = (const float4*)(in + row*E_);
    int t = threadIdx.x;
    float4 v = x[t];
    float s = v.x+v.y+v.z+v.w;
    float q = v.x*v.x+v.y*v.y+v.z*v.z+v.w*v.w;
    #pragma unroll
    for (int o=16;o;o>>=1){ s += __shfl_xor_sync(~0u,s,o); q += __shfl_xor_sync(~0u,q,o); }
    __shared__ float ss[8], sq[8];
    int w = t>>5, l = t&31;
    if (l==0){ ss[w]=s; sq[w]=q; }
    __syncthreads();
    if (t<32){
        float a = (l<8)? ss[l]:0.f, b = (l<8)? sq[l]:0.f;
        #pragma unroll
        for (int o=4;o;o>>=1){ a += __shfl_xor_sync(~0u,a,o); b += __shfl_xor_sync(~0u,b,o); }
        if (l==0){ ss[0]=a; sq[0]=b; }
    }
    __syncthreads();
    float mean = ss[0]*(1.0f/E_);
    float var  = sq[0]*(1.0f/E_) - mean*mean;
    float inv  = rsqrtf(fmaxf(var,0.f)+1e-12f);
    float4 g = ((const float4*)gamma)[t];
    float4 b = ((const float4*)beta)[t];
    float4 o;
    o.x=(v.x-mean)*inv*g.x+b.x; o.y=(v.y-mean)*inv*g.y+b.y;
    o.z=(v.z-mean)*inv*g.z+b.z; o.w=(v.w-mean)*inv*g.w+b.w;
    ((float4*)(out + row*E_))[t] = o;
}

/* ---------------- small prep kernels ------------------------------------------ */
__global__ void bias_sum_k(const float* __restrict__ a, const float* __restrict__ b){
    int i = blockIdx.x*256 + threadIdx.x;
    if (i < G4_) g_bias_sum[i] = a[i] + b[i];
}
__global__ void __launch_bounds__(256) vs_proj_k(const float* __restrict__ vs_p,
                                                 const float* __restrict__ op_W,
                                                 const float* __restrict__ op_b){
    int j = blockIdx.x*8 + (threadIdx.x>>5);
    int l = threadIdx.x & 31;
    const float* w = op_W + (long)j*E_;
    float acc = 0.f;
    for (int k=l; k<E_; k+=32) acc += psigm(vs_p[k]) * w[k];
    #pragma unroll
    for (int o=16;o;o>>=1) acc += __shfl_xor_sync(~0u,acc,o);
    if (l==0) g_tbuf[j] = acc + op_b[j];
}
__global__ void vs_gate_k(){
    int e = blockIdx.x*256 + threadIdx.x;
    if (e < E_) g_vsgv[e] = psigm(g_tbuf[E_+e]) * tanhf(g_tbuf[e]);
}
__global__ void zero_state_k(){
    int i = blockIdx.x*256 + threadIdx.x;
    if (i < B_*E_){ g_hbuf[0][i] = 0.f; g_hbuf[1][i] = 0.f; }
}
/* q = sigm(qs)*query ; k = sigm(ks)*mh  -> half outputs */
__global__ void scale_qkv_k(const float* __restrict__ qs, const float* __restrict__ ks){
    for (long i = (long)blockIdx.x*blockDim.x + threadIdx.x; i < (long)SB_*E_;
         i += (long)gridDim.x*blockDim.x){
        int e = (int)(i & (E_-1));
        gh_qsc[i] = __float2half(fsigm(qs[e]) * g_query[i]);
        gh_ksc[i] = __float2half(fsigm(ks[e]) * g_mh[i]);
    }
}
/* vT[b][e][s] = vsgv[e] * mh[s][b][e] -> half, tiled transpose */
__global__ void __launch_bounds__(256) vT_k(){
    __shared__ float Ts[32][33];
    const int b = blockIdx.z, s0 = blockIdx.x*32, e0 = blockIdx.y*32;
    const int tx = threadIdx.x & 31, ty = threadIdx.x >> 5;
    #pragma unroll
    for (int i=0;i<4;i++){
        int sl = ty*4+i;
        Ts[sl][tx] = g_mh[((long)(s0+sl)*B_ + b)*E_ + e0+tx];
    }
    __syncthreads();
    #pragma unroll
    for (int i=0;i<4;i++){
        int el = ty*4+i;
        gh_vT[((long)b*E_ + e0+el)*S_ + s0+tx] = __float2half(Ts[tx][el] * g_vsgv[e0+el]);
    }
}

/* ---------------- persistent LSTM: 128 blocks x 256 threads -------------------- */
#define LSTM_BLOCKS 128
#define LSTM_SMEM_BYTES (131072 + 32768 + 8192 + 1024 + 256)

__device__ __forceinline__ void fma2(unsigned long long &acc,
                                     unsigned long long a, unsigned long long b){
    asm("fma.rn.f32x2 %0, %1, %2, %0;" : "+l"(acc) : "l"(a), "l"(b));
}
__device__ __forceinline__ float f2sum(unsigned long long v){
    return __uint_as_float((unsigned)v) + __uint_as_float((unsigned)(v>>32));
}

__global__ void __launch_bounds__(256) lstm_persist_k(const float* __restrict__ gx,
                                                      const float* __restrict__ Whh,
                                                      float* __restrict__ rnn)
{
    extern __shared__ float sm[];
    float* w_sm    = sm;
    float* h_sm    = sm + 32768;
    float* red_sm  = h_sm + 8192;
    float* gate_sm = red_sm + 2048;

    const int tid = threadIdx.x;
    const int e_base = blockIdx.x*8;
    const int s_w = tid>>5;
    const int r   = tid&31;

    for (int rr = 0; rr < 32; rr++){
        long j = (long)((rr>>3)*E_ + e_base + (rr&7));
        const float4* src = (const float4*)(Whh + j*E_);
        for (int k4 = tid; k4 < 256; k4 += 256)
            *(float4*)&w_sm[(k4*32 + rr)*4] = src[k4];
    }

    float c_reg = 0.f;
    const int cb = tid>>3, ce = tid&7;

    __syncthreads();

    int parity = 0;
    for (int step = 0; step < S_; step++){
        const float4* hsrc = (const float4*)g_hbuf[parity];
        #pragma unroll
        for (int i = tid; i < 2048; i += 256)
            *(float4*)&h_sm[i*4] = __ldcg(hsrc + i);
        __syncthreads();

        unsigned long long acc0[8], acc1[8];
        #pragma unroll
        for (int b=0;b<8;b++){ acc0[b]=0ull; acc1[b]=0ull; }
        const int k4b = s_w*32;
        #pragma unroll 8
        for (int k4 = k4b; k4 < k4b+32; k4++){
            const unsigned long long* w2 = (const unsigned long long*)&w_sm[(k4*32 + r)*4];
            unsigned long long w01 = w2[0], w23 = w2[1];
            #pragma unroll
            for (int b=0;b<8;b++){
                const unsigned long long* h2p = (const unsigned long long*)&h_sm[b*E_ + k4*4];
                fma2(acc0[b], w01, h2p[0]);
                fma2(acc1[b], w23, h2p[1]);
            }
        }
        #pragma unroll
        for (int b=0;b<8;b++)
            red_sm[s_w*256 + r*8 + b] = f2sum(acc0[b]) + f2sum(acc1[b]);
        __syncthreads();

        {
            const int b2 = tid>>5, rr = tid&31;
            long j = (long)((rr>>3)*E_ + e_base + (rr&7));
            float g = gx[(long)step*B_*G4_ + (long)b2*G4_ + j];
            #pragma unroll
            for (int ss=0; ss<8; ss++) g += red_sm[ss*256 + rr*8 + b2];
            gate_sm[rr*8 + b2] = g;
        }
        __syncthreads();

        if (tid < 64){
            float gi = gate_sm[(0*8+ce)*8 + cb];
            float gf = gate_sm[(1*8+ce)*8 + cb];
            float gg = gate_sm[(2*8+ce)*8 + cb];
            float go = gate_sm[(3*8+ce)*8 + cb];
            c_reg = psigm(gf)*c_reg + psigm(gi)*tanhf(gg);
            float h = psigm(go)*tanhf(c_reg);
            int idx = cb*E_ + e_base + ce;
            __stcg(&g_hbuf[parity^1][idx], h);
            rnn[(long)step*B_*E_ + idx] = h;
            __threadfence();
        }
        __syncthreads();

        if (tid == 0){
            unsigned gen = g_bar_gen;
            __threadfence();
            if (atomicAdd(&g_bar_cnt, 1u) == LSTM_BLOCKS - 1u){
                g_bar_cnt = 0u;
                __threadfence();
                g_bar_gen = gen + 1u;
            } else {
                while (g_bar_gen == gen) __nanosleep(32);
            }
            __threadfence();
        }
        __syncthreads();
        parity ^= 1;
    }
}

/* ---------------- softmax over rows of length S ------------------------------- */
__global__ void __launch_bounds__(256) softmax_k(float* __restrict__ sc){
    float* p = sc + (long)blockIdx.x*S_;
    int t = threadIdx.x;
    float4 v0 = ((float4*)p)[t], v1 = ((float4*)p)[t+256];
    float mx = fmaxf(fmaxf(fmaxf(v0.x,v0.y),fmaxf(v0.z,v0.w)),
                     fmaxf(fmaxf(v1.x,v1.y),fmaxf(v1.z,v1.w)));
    #pragma unroll
    for (int o=16;o;o>>=1) mx = fmaxf(mx, __shfl_xor_sync(~0u,mx,o));
    __shared__ float sm[8];
    int w=t>>5, l=t&31;
    if (l==0) sm[w]=mx;
    __syncthreads();
    if (t<32){ float a=(l<8)?sm[l]:-1e30f;
        #pragma unroll
        for(int o=4;o;o>>=1) a=fmaxf(a,__shfl_xor_sync(~0u,a,o));
        if(l==0) sm[0]=a; }
    __syncthreads();
    mx = sm[0];
    v0.x=__expf(v0.x-mx); v0.y=__expf(v0.y-mx); v0.z=__expf(v0.z-mx); v0.w=__expf(v0.w-mx);
    v1.x=__expf(v1.x-mx); v1.y=__expf(v1.y-mx); v1.z=__expf(v1.z-mx); v1.w=__expf(v1.w-mx);
    float s = v0.x+v0.y+v0.z+v0.w+v1.x+v1.y+v1.z+v1.w;
    #pragma unroll
    for (int o=16;o;o>>=1) s += __shfl_xor_sync(~0u,s,o);
    __shared__ float s2[8];
    if (l==0) s2[w]=s;
    __syncthreads();
    if (t<32){ float a=(l<8)?s2[l]:0.f;
        #pragma unroll
        for(int o=4;o;o>>=1) a+=__shfl_xor_sync(~0u,a,o);
        if(l==0) s2[0]=a; }
    __syncthreads();
    float inv = 1.0f/s2[0];
    v0.x*=inv; v0.y*=inv; v0.z*=inv; v0.w*=inv;
    v1.x*=inv; v1.y*=inv; v1.z*=inv; v1.w*=inv;
    ((float4*)p)[t]=v0; ((float4*)p)[t+256]=v1;
}

/* ---------------- host side ---------------------------------------------------- */
static float* devp(const void* sym){ void* p=0; cudaGetSymbolAddress(&p,sym); return (float*)p; }
static __half* devph(const void* sym){ void* p=0; cudaGetSymbolAddress(&p,sym); return (__half*)p; }

extern "C" void kernel_launch(void* const* d_in, const int* in_sizes, int n_in,
                              void* d_out, int out_size)
{
    const float* inputs = (const float*)d_in[0];
    const float* mask   = (const float*)d_in[1];
    const float* Wih    = (const float*)d_in[3];
    const float* Whh    = (const float*)d_in[4];
    const float* bih    = (const float*)d_in[5];
    const float* bhh    = (const float*)d_in[6];
    const float* lnstart_g=(const float*)d_in[7],  *lnstart_b=(const float*)d_in[8];
    const float* lnmem_g  =(const float*)d_in[9],  *lnmem_b  =(const float*)d_in[10];
    const float* lnmid_g  =(const float*)d_in[11], *lnmid_b  =(const float*)d_in[12];
    const float* lnff_g   =(const float*)d_in[13], *lnff_b   =(const float*)d_in[14];
    const float* lnxff_g  =(const float*)d_in[15], *lnxff_b  =(const float*)d_in[16];
    const float* qln_g    =(const float*)d_in[17], *qln_b    =(const float*)d_in[18];
    const float* qs    = (const float*)d_in[19];
    const float* ks_p  = (const float*)d_in[20];
    const float* vs_p  = (const float*)d_in[21];
    const float* op_W  = (const float*)d_in[22];
    const float* op_b  = (const float*)d_in[23];
    const float* ql_W  = (const float*)d_in[24];
    const float* ql_b  = (const float*)d_in[25];
    const float* boom_W= (const float*)d_in[26];
    const float* boom_b= (const float*)d_in[27];
    float* out = (float*)d_out;

    float *xln=devp(g_xln), *gx=devp(g_gx), *rnn=devp(g_rnn), *mh=devp(g_mh),
          *hmid=devp(g_hmid), *qpre=devp(g_qpre), *query=devp(g_query),
          *scores=devp(g_scores), *h2=devp(g_h2), *xff=devp(g_xff),
          *lnffo=devp(g_lnffo), *bsum=devp(g_bias_sum);
    __half *hxln=devph(gh_xln), *hWih=devph(gh_Wih), *hhmid=devph(gh_hmid),
           *hqlW=devph(gh_qlW), *hqsc=devph(gh_qsc), *hksc=devph(gh_ksc),
           *hvT=devph(gh_vT), *hsc=devph(gh_sc), *hxff=devph(gh_xff),
           *hbmW=devph(gh_bmW);

    cudaFuncSetAttribute(lstm_persist_k,
                         cudaFuncAttributeMaxDynamicSharedMemorySize, LSTM_SMEM_BYTES);

    /* launch order: #6 is the gx GEMM (ncu -s 5 -c 1 captures it) */
    bias_sum_k<<<16,256>>>(bih,bhh);                               /* 1 */
    ln_kernel<<<SB_,256>>>(inputs, xln, lnstart_g, lnstart_b);     /* 2 */
    cvt_h_k<<<2048,256>>>(xln,  hxln, (long)SB_*E_);               /* 3 */
    cvt_h_k<<<2048,256>>>(Wih,  hWih, (long)G4_*E_);               /* 4 */
    vs_proj_k<<<256,256>>>(vs_p,op_W,op_b);                        /* 5 */

    /* gx = xln @ Wih^T + (bih+bhh) : fp16 mma */
    gemm_h<<<dim3(32,128,1),256>>>(hxln,hWih,bsum,0, gx,           /* 6 */
        E_, E_,E_,G4_,0, 0,0,0,0, 0, 1.0f, 0);

    vs_gate_k<<<4,256>>>();
    zero_state_k<<<32,256>>>();

    lstm_persist_k<<<LSTM_BLOCKS,256,LSTM_SMEM_BYTES>>>(gx, Whh, rnn);

    ln_kernel<<<SB_,256>>>(rnn, mh,   lnmem_g, lnmem_b);
    ln_kernel<<<SB_,256>>>(rnn, hmid, lnmid_g, lnmid_b);
    cvt_h_k<<<2048,256>>>(hmid, hhmid, (long)SB_*E_);
    cvt_h_k<<<512,256>>>(ql_W,  hqlW, (long)E_*E_);
    cvt_h_k<<<512,256>>>(boom_W, hbmW, (long)E_*E_);

    /* query projection */
    gemm_h<<<dim3(8,128,1),256>>>(hhmid,hqlW,ql_b,0, qpre,
        E_, E_,E_,E_,0, 0,0,0,0, 0, 1.0f, 0);
    ln_kernel<<<SB_,256>>>(qpre, query, qln_g, qln_b);
    scale_qkv_k<<<1024,256>>>(qs, ks_p);
    vT_k<<<dim3(S_/32,E_/32,B_),256>>>();

    /* scores = q.k/sqrt(E) + mask : batched NT, causal-skip */
    gemm_h<<<dim3(16,16,8),256>>>(hqsc,hksc,0,mask, scores,
        E_, B_*E_, B_*E_, S_, S_, E_, E_, (long)S_*S_, 0, 1, 0.03125f, 1);

    softmax_k<<<B_*S_,256>>>(scores);
    cvt_h_k<<<4096,256>>>(scores, hsc, (long)B_*S_*S_);

    /* mix = w @ vT^T + hmid : batched NT, causal K-limit */
    gemm_h<<<dim3(8,16,8),256>>>(hsc,hvT,0,hmid, h2,
        S_, S_, S_, B_*E_, B_*E_, (long)S_*S_, (long)E_*S_, E_, E_, 2, 1.0f, 1);

    /* boom */
    ln_kernel<<<SB_,256>>>(h2, xff,   lnxff_g, lnxff_b);
    ln_kernel<<<SB_,256>>>(h2, lnffo, lnff_g,  lnff_b);
    cvt_h_k<<<2048,256>>>(xff, hxff, (long)SB_*E_);
    gemm_h<<<dim3(8,128,1),256>>>(hxff,hbmW,boom_b,lnffo, out,
        E_, E_,E_,E_,E_, 0,0,0,0, 3, 1.0f, 0);
}